// round 1
// baseline (speedup 1.0000x reference)
#include <cuda_runtime.h>
#include <math.h>

#define NLV 16
#define LOG2T 19
#define TMASK ((1u << LOG2T) - 1u)
#define P1 2654435761u
#define P2 805459861u

struct LP {
    float g[NLV];   // grid = 2/res (f32, matches reference)
    float ig[NLV];  // 1/grid = res/2 (exact in f32)
};

__global__ void __launch_bounds__(256)
ingp_hash_kernel(const float* __restrict__ x,
                 const float2* __restrict__ emb,
                 float4* __restrict__ out,
                 int N, LP lp)
{
    int n = blockIdx.x * 256 + threadIdx.x;
    if (n >= N) return;

    float xx = __ldcs(x + 3 * n + 0);
    float xy = __ldcs(x + 3 * n + 1);
    float xz = __ldcs(x + 3 * n + 2);

    // clip to box then shift by -BOX_MIN (= +1)
    float px = fminf(fmaxf(xx, -1.0f), 1.0f) + 1.0f;
    float py = fminf(fmaxf(xy, -1.0f), 1.0f) + 1.0f;
    float pz = fminf(fmaxf(xz, -1.0f), 1.0f) + 1.0f;

    float2 prev = make_float2(0.0f, 0.0f);

#pragma unroll
    for (int l = 0; l < NLV; l++) {
        const float2* __restrict__ t = emb + ((size_t)l << LOG2T);
        float g  = lp.g[l];
        float ig = lp.ig[l];

        float tx = px * ig;
        float ty = py * ig;
        float tz = pz * ig;
        int bx = __float2int_rd(tx);
        int by = __float2int_rd(ty);
        int bz = __float2int_rd(tz);
        // w = (p - b*g) * (1/g)
        float wx = fmaf(-(float)bx, g, px) * ig;
        float wy = fmaf(-(float)by, g, py) * ig;
        float wz = fmaf(-(float)bz, g, pz) * ig;

        unsigned hx0 = (unsigned)bx;
        unsigned hx1 = hx0 + 1u;
        unsigned hy0 = (unsigned)by * P1;
        unsigned hy1 = hy0 + P1;
        unsigned hz0 = (unsigned)bz * P2;
        unsigned hz1 = hz0 + P2;

        unsigned a00 = hx0 ^ hy0;
        unsigned a01 = hx0 ^ hy1;
        unsigned a10 = hx1 ^ hy0;
        unsigned a11 = hx1 ^ hy1;

        // e[dx][dy][dz]
        float2 e000 = __ldg(t + ((a00 ^ hz0) & TMASK));
        float2 e001 = __ldg(t + ((a00 ^ hz1) & TMASK));
        float2 e010 = __ldg(t + ((a01 ^ hz0) & TMASK));
        float2 e011 = __ldg(t + ((a01 ^ hz1) & TMASK));
        float2 e100 = __ldg(t + ((a10 ^ hz0) & TMASK));
        float2 e101 = __ldg(t + ((a10 ^ hz1) & TMASK));
        float2 e110 = __ldg(t + ((a11 ^ hz0) & TMASK));
        float2 e111 = __ldg(t + ((a11 ^ hz1) & TMASK));

        float ux = 1.0f - wx;
        float uy = 1.0f - wy;
        float uz = 1.0f - wz;

        float s00 = uy * uz;   // dy=0, dz=0
        float s01 = uy * wz;   // dy=0, dz=1
        float s10 = wy * uz;   // dy=1, dz=0
        float s11 = wy * wz;   // dy=1, dz=1

        float w000 = ux * s00, w001 = ux * s01, w010 = ux * s10, w011 = ux * s11;
        float w100 = wx * s00, w101 = wx * s01, w110 = wx * s10, w111 = wx * s11;

        float rx = w000 * e000.x;
        float ry = w000 * e000.y;
        rx = fmaf(w001, e001.x, rx); ry = fmaf(w001, e001.y, ry);
        rx = fmaf(w010, e010.x, rx); ry = fmaf(w010, e010.y, ry);
        rx = fmaf(w011, e011.x, rx); ry = fmaf(w011, e011.y, ry);
        rx = fmaf(w100, e100.x, rx); ry = fmaf(w100, e100.y, ry);
        rx = fmaf(w101, e101.x, rx); ry = fmaf(w101, e101.y, ry);
        rx = fmaf(w110, e110.x, rx); ry = fmaf(w110, e110.y, ry);
        rx = fmaf(w111, e111.x, rx); ry = fmaf(w111, e111.y, ry);

        if (l & 1) {
            float4 v = make_float4(prev.x, prev.y, rx, ry);
            __stcs(out + (size_t)n * 8 + (l >> 1), v);
        } else {
            prev.x = rx;
            prev.y = ry;
        }
    }
}

extern "C" void kernel_launch(void* const* d_in, const int* in_sizes, int n_in,
                              void* d_out, int out_size)
{
    const float*  x   = (const float*)d_in[0];
    const float2* emb = (const float2*)d_in[1];
    int N = in_sizes[0] / 3;

    LP lp;
    // replicate np.floor(COARSE * b**k) with the same libm double path
    double b = exp((log(512.0) - log(16.0)) / 15.0);
    for (int l = 0; l < NLV; l++) {
        float r = (float)floor(16.0 * pow(b, (double)l));
        lp.g[l]  = 2.0f / r;   // f32 division, matches jnp grid
        lp.ig[l] = r * 0.5f;   // exact
    }

    int blocks = (N + 255) / 256;
    if (blocks > 0) {
        ingp_hash_kernel<<<blocks, 256>>>(x, emb, (float4*)d_out, N, lp);
    }
}

// round 2
// speedup vs baseline: 2.1174x; 2.1174x over previous
#include <cuda_runtime.h>
#include <math.h>

#define NLV 16
#define LOG2T 19
#define TMASK ((1u << LOG2T) - 1u)
#define P1 2654435761u
#define P2 805459861u

#define NBUCKET (1 << 18)   // 64^3 Morton buckets
#define MAXN (1 << 20)

__device__ int g_hist[NBUCKET];
__device__ int g_off[NBUCKET];
__device__ int g_partials[256];
__device__ int g_key[MAXN];
__device__ int g_perm[MAXN];

struct LP {
    float g[NLV];   // grid = 2/res
    float ig[NLV];  // 1/grid = res/2
};

// ---------- Morton bucketing ----------
__device__ __forceinline__ unsigned spread3(unsigned v) {
    v &= 0x3FF;
    v = (v | (v << 16)) & 0x030000FF;
    v = (v | (v << 8))  & 0x0300F00F;
    v = (v | (v << 4))  & 0x030C30C3;
    v = (v | (v << 2))  & 0x09249249;
    return v;
}

__global__ void zero_hist_kernel() {
    int i = blockIdx.x * 1024 + threadIdx.x;
    g_hist[i] = 0;
}

__global__ void hist_kernel(const float* __restrict__ x, int N) {
    int n = blockIdx.x * 256 + threadIdx.x;
    if (n >= N) return;
    float px = fminf(fmaxf(x[3 * n + 0], -1.0f), 1.0f) + 1.0f;  // [0,2]
    float py = fminf(fmaxf(x[3 * n + 1], -1.0f), 1.0f) + 1.0f;
    float pz = fminf(fmaxf(x[3 * n + 2], -1.0f), 1.0f) + 1.0f;
    unsigned ix = min(63u, (unsigned)(px * 32.0f));
    unsigned iy = min(63u, (unsigned)(py * 32.0f));
    unsigned iz = min(63u, (unsigned)(pz * 32.0f));
    unsigned key = (spread3(ix) << 2) | (spread3(iy) << 1) | spread3(iz);
    g_key[n] = (int)key;
    atomicAdd(&g_hist[key], 1);
}

// Exclusive scan of g_hist (262144 = 256 blocks x 1024) into g_off.
__global__ void scan1_kernel() {
    int gid = blockIdx.x * 1024 + threadIdx.x;
    int v = g_hist[gid];
    int lane = threadIdx.x & 31, w = threadIdx.x >> 5;
    int s = v;
#pragma unroll
    for (int d = 1; d < 32; d <<= 1) {
        int t = __shfl_up_sync(0xFFFFFFFFu, s, d);
        if (lane >= d) s += t;
    }
    __shared__ int wsum[32];
    if (lane == 31) wsum[w] = s;
    __syncthreads();
    if (w == 0) {
        int t = wsum[lane];
        int ss = t;
#pragma unroll
        for (int d = 1; d < 32; d <<= 1) {
            int u = __shfl_up_sync(0xFFFFFFFFu, ss, d);
            if (lane >= d) ss += u;
        }
        wsum[lane] = ss - t;   // exclusive warp offsets
    }
    __syncthreads();
    int excl = s - v + wsum[w];
    g_off[gid] = excl;
    if (threadIdx.x == 1023) g_partials[blockIdx.x] = excl + v;
}

__global__ void scan2_kernel() {   // 1 block, 256 threads
    int v = g_partials[threadIdx.x];
    int lane = threadIdx.x & 31, w = threadIdx.x >> 5;
    int s = v;
#pragma unroll
    for (int d = 1; d < 32; d <<= 1) {
        int t = __shfl_up_sync(0xFFFFFFFFu, s, d);
        if (lane >= d) s += t;
    }
    __shared__ int wsum[8];
    if (lane == 31) wsum[w] = s;
    __syncthreads();
    int woff = 0;
    for (int i = 0; i < w; i++) woff += wsum[i];
    g_partials[threadIdx.x] = s - v + woff;
}

__global__ void scan3_kernel() {
    int gid = blockIdx.x * 1024 + threadIdx.x;
    g_off[gid] += g_partials[blockIdx.x];
}

__global__ void scatter_kernel(int N) {
    int n = blockIdx.x * 256 + threadIdx.x;
    if (n >= N) return;
    int key = g_key[n];
    int pos = atomicAdd(&g_off[key], 1);
    g_perm[pos] = n;
}

// ---------- main encoder ----------
__global__ void __launch_bounds__(256)
ingp_hash_kernel(const float* __restrict__ x,
                 const float2* __restrict__ emb,
                 float4* __restrict__ out,
                 int N, LP lp, int use_perm)
{
    int i = blockIdx.x * 256 + threadIdx.x;
    if (i >= N) return;
    int n = use_perm ? __ldg(g_perm + i) : i;

    float xx = __ldg(x + 3 * n + 0);
    float xy = __ldg(x + 3 * n + 1);
    float xz = __ldg(x + 3 * n + 2);

    float px = fminf(fmaxf(xx, -1.0f), 1.0f) + 1.0f;
    float py = fminf(fmaxf(xy, -1.0f), 1.0f) + 1.0f;
    float pz = fminf(fmaxf(xz, -1.0f), 1.0f) + 1.0f;

    float2 prev = make_float2(0.0f, 0.0f);

#pragma unroll
    for (int l = 0; l < NLV; l++) {
        const float2* __restrict__ t = emb + ((size_t)l << LOG2T);
        float g  = lp.g[l];
        float ig = lp.ig[l];

        int bx = __float2int_rd(px * ig);
        int by = __float2int_rd(py * ig);
        int bz = __float2int_rd(pz * ig);
        float wx = fmaf(-(float)bx, g, px) * ig;
        float wy = fmaf(-(float)by, g, py) * ig;
        float wz = fmaf(-(float)bz, g, pz) * ig;

        unsigned hx0 = (unsigned)bx;
        unsigned hx1 = hx0 + 1u;
        unsigned hy0 = (unsigned)by * P1;
        unsigned hy1 = hy0 + P1;
        unsigned hz0 = (unsigned)bz * P2;
        unsigned hz1 = hz0 + P2;

        unsigned a00 = hx0 ^ hy0;
        unsigned a01 = hx0 ^ hy1;
        unsigned a10 = hx1 ^ hy0;
        unsigned a11 = hx1 ^ hy1;

        float2 e000 = __ldg(t + ((a00 ^ hz0) & TMASK));
        float2 e001 = __ldg(t + ((a00 ^ hz1) & TMASK));
        float2 e010 = __ldg(t + ((a01 ^ hz0) & TMASK));
        float2 e011 = __ldg(t + ((a01 ^ hz1) & TMASK));
        float2 e100 = __ldg(t + ((a10 ^ hz0) & TMASK));
        float2 e101 = __ldg(t + ((a10 ^ hz1) & TMASK));
        float2 e110 = __ldg(t + ((a11 ^ hz0) & TMASK));
        float2 e111 = __ldg(t + ((a11 ^ hz1) & TMASK));

        float ux = 1.0f - wx;
        float uy = 1.0f - wy;
        float uz = 1.0f - wz;

        float s00 = uy * uz;
        float s01 = uy * wz;
        float s10 = wy * uz;
        float s11 = wy * wz;

        float w000 = ux * s00, w001 = ux * s01, w010 = ux * s10, w011 = ux * s11;
        float w100 = wx * s00, w101 = wx * s01, w110 = wx * s10, w111 = wx * s11;

        float rx = w000 * e000.x;
        float ry = w000 * e000.y;
        rx = fmaf(w001, e001.x, rx); ry = fmaf(w001, e001.y, ry);
        rx = fmaf(w010, e010.x, rx); ry = fmaf(w010, e010.y, ry);
        rx = fmaf(w011, e011.x, rx); ry = fmaf(w011, e011.y, ry);
        rx = fmaf(w100, e100.x, rx); ry = fmaf(w100, e100.y, ry);
        rx = fmaf(w101, e101.x, rx); ry = fmaf(w101, e101.y, ry);
        rx = fmaf(w110, e110.x, rx); ry = fmaf(w110, e110.y, ry);
        rx = fmaf(w111, e111.x, rx); ry = fmaf(w111, e111.y, ry);

        if (l & 1) {
            float4 v = make_float4(prev.x, prev.y, rx, ry);
            __stcs(out + (size_t)n * 8 + (l >> 1), v);
        } else {
            prev.x = rx;
            prev.y = ry;
        }
    }
}

extern "C" void kernel_launch(void* const* d_in, const int* in_sizes, int n_in,
                              void* d_out, int out_size)
{
    const float*  x   = (const float*)d_in[0];
    const float2* emb = (const float2*)d_in[1];
    int N = in_sizes[0] / 3;

    LP lp;
    double b = exp((log(512.0) - log(16.0)) / 15.0);
    for (int l = 0; l < NLV; l++) {
        float r = (float)floor(16.0 * pow(b, (double)l));
        lp.g[l]  = 2.0f / r;
        lp.ig[l] = r * 0.5f;
    }

    int blocks = (N + 255) / 256;
    if (blocks <= 0) return;

    if (N <= MAXN) {
        zero_hist_kernel<<<NBUCKET / 1024, 1024>>>();
        hist_kernel<<<blocks, 256>>>(x, N);
        scan1_kernel<<<NBUCKET / 1024, 1024>>>();
        scan2_kernel<<<1, 256>>>();
        scan3_kernel<<<NBUCKET / 1024, 1024>>>();
        scatter_kernel<<<blocks, 256>>>(N);
        ingp_hash_kernel<<<blocks, 256>>>(x, emb, (float4*)d_out, N, lp, 1);
    } else {
        ingp_hash_kernel<<<blocks, 256>>>(x, emb, (float4*)d_out, N, lp, 0);
    }
}

// round 3
// speedup vs baseline: 2.1211x; 1.0017x over previous
#include <cuda_runtime.h>
#include <math.h>

#define NLV 16
#define LOG2T 19
#define TMASK ((1u << LOG2T) - 1u)
#define P1 2654435761u
#define P2 805459861u

#define NBUCKET (1 << 18)   // 64^3 Morton buckets
#define MAXN (1 << 20)

__device__ int g_hist[NBUCKET];
__device__ int g_off[NBUCKET];
__device__ int g_partials[256];
__device__ int g_key[MAXN];
__device__ int g_perm[MAXN];

struct LP {
    float g[NLV];   // grid = 2/res
    float ig[NLV];  // 1/grid = res/2
};

// ---------- Morton bucketing ----------
__device__ __forceinline__ unsigned spread3(unsigned v) {
    v &= 0x3FF;
    v = (v | (v << 16)) & 0x030000FF;
    v = (v | (v << 8))  & 0x0300F00F;
    v = (v | (v << 4))  & 0x030C30C3;
    v = (v | (v << 2))  & 0x09249249;
    return v;
}

__global__ void zero_hist_kernel() {
    int i = blockIdx.x * 1024 + threadIdx.x;
    g_hist[i] = 0;
}

__global__ void hist_kernel(const float* __restrict__ x, int N) {
    int n = blockIdx.x * 256 + threadIdx.x;
    if (n >= N) return;
    float px = fminf(fmaxf(x[3 * n + 0], -1.0f), 1.0f) + 1.0f;  // [0,2]
    float py = fminf(fmaxf(x[3 * n + 1], -1.0f), 1.0f) + 1.0f;
    float pz = fminf(fmaxf(x[3 * n + 2], -1.0f), 1.0f) + 1.0f;
    unsigned ix = min(63u, (unsigned)(px * 32.0f));
    unsigned iy = min(63u, (unsigned)(py * 32.0f));
    unsigned iz = min(63u, (unsigned)(pz * 32.0f));
    unsigned key = (spread3(ix) << 2) | (spread3(iy) << 1) | spread3(iz);
    g_key[n] = (int)key;
    atomicAdd(&g_hist[key], 1);
}

// Exclusive scan of g_hist (262144 = 256 blocks x 1024) into g_off.
__global__ void scan1_kernel() {
    int gid = blockIdx.x * 1024 + threadIdx.x;
    int v = g_hist[gid];
    int lane = threadIdx.x & 31, w = threadIdx.x >> 5;
    int s = v;
#pragma unroll
    for (int d = 1; d < 32; d <<= 1) {
        int t = __shfl_up_sync(0xFFFFFFFFu, s, d);
        if (lane >= d) s += t;
    }
    __shared__ int wsum[32];
    if (lane == 31) wsum[w] = s;
    __syncthreads();
    if (w == 0) {
        int t = wsum[lane];
        int ss = t;
#pragma unroll
        for (int d = 1; d < 32; d <<= 1) {
            int u = __shfl_up_sync(0xFFFFFFFFu, ss, d);
            if (lane >= d) ss += u;
        }
        wsum[lane] = ss - t;   // exclusive warp offsets
    }
    __syncthreads();
    int excl = s - v + wsum[w];
    g_off[gid] = excl;
    if (threadIdx.x == 1023) g_partials[blockIdx.x] = excl + v;
}

__global__ void scan2_kernel() {   // 1 block, 256 threads
    int v = g_partials[threadIdx.x];
    int lane = threadIdx.x & 31, w = threadIdx.x >> 5;
    int s = v;
#pragma unroll
    for (int d = 1; d < 32; d <<= 1) {
        int t = __shfl_up_sync(0xFFFFFFFFu, s, d);
        if (lane >= d) s += t;
    }
    __shared__ int wsum[8];
    if (lane == 31) wsum[w] = s;
    __syncthreads();
    int woff = 0;
    for (int i = 0; i < w; i++) woff += wsum[i];
    g_partials[threadIdx.x] = s - v + woff;
}

__global__ void scan3_kernel() {
    int gid = blockIdx.x * 1024 + threadIdx.x;
    g_off[gid] += g_partials[blockIdx.x];
}

__global__ void scatter_kernel(int N) {
    int n = blockIdx.x * 256 + threadIdx.x;
    if (n >= N) return;
    int key = g_key[n];
    int pos = atomicAdd(&g_off[key], 1);
    g_perm[pos] = n;
}

// ---------- main encoder ----------
__global__ void __launch_bounds__(256)
ingp_hash_kernel(const float* __restrict__ x,
                 const float2* __restrict__ emb,
                 float4* __restrict__ out,
                 int N, LP lp, int use_perm)
{
    int i = blockIdx.x * 256 + threadIdx.x;
    if (i >= N) return;
    int n = use_perm ? __ldg(g_perm + i) : i;

    float xx = __ldg(x + 3 * n + 0);
    float xy = __ldg(x + 3 * n + 1);
    float xz = __ldg(x + 3 * n + 2);

    float px = fminf(fmaxf(xx, -1.0f), 1.0f) + 1.0f;
    float py = fminf(fmaxf(xy, -1.0f), 1.0f) + 1.0f;
    float pz = fminf(fmaxf(xz, -1.0f), 1.0f) + 1.0f;

    float2 prev = make_float2(0.0f, 0.0f);

#pragma unroll
    for (int l = 0; l < NLV; l++) {
        const float2* __restrict__ t = emb + ((size_t)l << LOG2T);
        float g  = lp.g[l];
        float ig = lp.ig[l];

        int bx = __float2int_rd(px * ig);
        int by = __float2int_rd(py * ig);
        int bz = __float2int_rd(pz * ig);
        float wx = fmaf(-(float)bx, g, px) * ig;
        float wy = fmaf(-(float)by, g, py) * ig;
        float wz = fmaf(-(float)bz, g, pz) * ig;

        unsigned hx0 = (unsigned)bx;
        unsigned hx1 = hx0 + 1u;
        unsigned hy0 = (unsigned)by * P1;
        unsigned hy1 = hy0 + P1;
        unsigned hz0 = (unsigned)bz * P2;
        unsigned hz1 = hz0 + P2;

        unsigned a00 = hx0 ^ hy0;
        unsigned a01 = hx0 ^ hy1;
        unsigned a10 = hx1 ^ hy0;
        unsigned a11 = hx1 ^ hy1;

        float2 e000 = __ldg(t + ((a00 ^ hz0) & TMASK));
        float2 e001 = __ldg(t + ((a00 ^ hz1) & TMASK));
        float2 e010 = __ldg(t + ((a01 ^ hz0) & TMASK));
        float2 e011 = __ldg(t + ((a01 ^ hz1) & TMASK));
        float2 e100 = __ldg(t + ((a10 ^ hz0) & TMASK));
        float2 e101 = __ldg(t + ((a10 ^ hz1) & TMASK));
        float2 e110 = __ldg(t + ((a11 ^ hz0) & TMASK));
        float2 e111 = __ldg(t + ((a11 ^ hz1) & TMASK));

        float ux = 1.0f - wx;
        float uy = 1.0f - wy;
        float uz = 1.0f - wz;

        float s00 = uy * uz;
        float s01 = uy * wz;
        float s10 = wy * uz;
        float s11 = wy * wz;

        float w000 = ux * s00, w001 = ux * s01, w010 = ux * s10, w011 = ux * s11;
        float w100 = wx * s00, w101 = wx * s01, w110 = wx * s10, w111 = wx * s11;

        float rx = w000 * e000.x;
        float ry = w000 * e000.y;
        rx = fmaf(w001, e001.x, rx); ry = fmaf(w001, e001.y, ry);
        rx = fmaf(w010, e010.x, rx); ry = fmaf(w010, e010.y, ry);
        rx = fmaf(w011, e011.x, rx); ry = fmaf(w011, e011.y, ry);
        rx = fmaf(w100, e100.x, rx); ry = fmaf(w100, e100.y, ry);
        rx = fmaf(w101, e101.x, rx); ry = fmaf(w101, e101.y, ry);
        rx = fmaf(w110, e110.x, rx); ry = fmaf(w110, e110.y, ry);
        rx = fmaf(w111, e111.x, rx); ry = fmaf(w111, e111.y, ry);

        if (l & 1) {
            float4 v = make_float4(prev.x, prev.y, rx, ry);
            __stcs(out + (size_t)n * 8 + (l >> 1), v);
        } else {
            prev.x = rx;
            prev.y = ry;
        }
    }
}

extern "C" void kernel_launch(void* const* d_in, const int* in_sizes, int n_in,
                              void* d_out, int out_size)
{
    const float*  x   = (const float*)d_in[0];
    const float2* emb = (const float2*)d_in[1];
    int N = in_sizes[0] / 3;

    LP lp;
    double b = exp((log(512.0) - log(16.0)) / 15.0);
    for (int l = 0; l < NLV; l++) {
        float r = (float)floor(16.0 * pow(b, (double)l));
        lp.g[l]  = 2.0f / r;
        lp.ig[l] = r * 0.5f;
    }

    int blocks = (N + 255) / 256;
    if (blocks <= 0) return;

    if (N <= MAXN) {
        zero_hist_kernel<<<NBUCKET / 1024, 1024>>>();
        hist_kernel<<<blocks, 256>>>(x, N);
        scan1_kernel<<<NBUCKET / 1024, 1024>>>();
        scan2_kernel<<<1, 256>>>();
        scan3_kernel<<<NBUCKET / 1024, 1024>>>();
        scatter_kernel<<<blocks, 256>>>(N);
        ingp_hash_kernel<<<blocks, 256>>>(x, emb, (float4*)d_out, N, lp, 1);
    } else {
        ingp_hash_kernel<<<blocks, 256>>>(x, emb, (float4*)d_out, N, lp, 0);
    }
}